// round 6
// baseline (speedup 1.0000x reference)
#include <cuda_runtime.h>

// ---------------------------------------------------------------------------
// R6: Fused 2-layer LSTM (H=4, I=2, T=50) + readout, 4 elements/thread.
// R4==R5 (211.9us both) despite 2x ILP -> per-element THROUGHPUT wall, and the
// unprinted pipe is MUFU (~10 tanh.approx.f32 per element-step ~= 120-145us of
// MUFU work, plausibly saturated). This round cuts MUFU 30%:
//   i/f/o gate sigmoids of TWO elements are paired into one
//   tanh.approx.f16x2 (1 MUFU op / 2 sigmoids). g-tanh and c-tanh stay f32.
//   Pack/unpack cvts ride the idle alu pipe; the 0.5*t+0.5 affine becomes one
//   HFMA2. MUFU per element-step: 10 -> 7.
// Everything else as R5: packed fma.rn.f32x2 gate MACs, quad shfl broadcast,
// recurrent-terms-first accumulation, coalesced float4 store.
// ---------------------------------------------------------------------------

#define T_STEPS 50
typedef unsigned long long ull;

__device__ __forceinline__ ull pk2(float lo, float hi) {
    ull r; asm("mov.b64 %0, {%1, %2};" : "=l"(r) : "f"(lo), "f"(hi)); return r;
}
__device__ __forceinline__ void upk2(ull v, float& lo, float& hi) {
    asm("mov.b64 {%0, %1}, %2;" : "=f"(lo), "=f"(hi) : "l"(v));
}
__device__ __forceinline__ ull ffma2(ull a, ull b, ull c) {
    ull d; asm("fma.rn.f32x2 %0, %1, %2, %3;" : "=l"(d) : "l"(a), "l"(b), "l"(c));
    return d;
}
__device__ __forceinline__ float tanhap(float x) {
    float r; asm("tanh.approx.f32 %0, %1;" : "=f"(r) : "f"(x)); return r;
}
__device__ __forceinline__ float ex2f(float x) {
    float r; asm("ex2.approx.f32 %0, %1;" : "=f"(r) : "f"(x)); return r;
}
__device__ __forceinline__ float rcpf(float x) {
    float r; asm("rcp.approx.f32 %0, %1;" : "=f"(r) : "f"(x)); return r;
}

// Two sigmoids in one MUFU op: pre-acts already scaled by 0.5 (folded into
// weights), so sigma = 0.5 + 0.5*tanh(y). Computed in f16x2; conversions go
// to the alu pipe, the affine to one HFMA2.
__device__ __forceinline__ void sig2(float ya, float yb, float& sa, float& sb) {
    unsigned p;
    asm("{\n\t"
        "cvt.rn.f16x2.f32 %0, %2, %1;\n\t"   // upper=yb, lower=ya
        "tanh.approx.f16x2 %0, %0;\n\t"
        "fma.rn.f16x2 %0, %0, %3, %3;\n\t"   // 0.5*t + 0.5 (both halves)
        "}" : "=r"(p) : "f"(ya), "f"(yb), "r"(0x38003800u));
    asm("{\n\t"
        ".reg .b16 lo, hi;\n\t"
        "mov.b32 {lo, hi}, %2;\n\t"
        "cvt.f32.f16 %0, lo;\n\t"
        "cvt.f32.f16 %1, hi;\n\t"
        "}" : "=f"(sa), "=f"(sb) : "r"(p));
}

#define NE 4   // batch elements per thread (processed as 2 pairs)

__global__ __launch_bounds__(128, 3) void lstm_fused4h(
    const float* __restrict__ x,     // [B, T, 2]
    const float* __restrict__ Wih0,  // [16, 2]
    const float* __restrict__ Whh0,  // [16, 4]
    const float* __restrict__ bih0,
    const float* __restrict__ bhh0,
    const float* __restrict__ Wih1,  // [16, 4]
    const float* __restrict__ Whh1,  // [16, 4]
    const float* __restrict__ bih1,
    const float* __restrict__ bhh1,
    const float* __restrict__ Wout,  // [1, 200], col = t*4 + u
    const float* __restrict__ bout,
    float* __restrict__ out,
    int B)
{
    int g = blockIdx.x * 128 + threadIdx.x;
    int q = g >> 2;            // quad owns elements NE*q .. NE*q+3
    int u = g & 3;             // hidden unit owned by this lane
    int eA = NE * q;
    if (eA >= B) return;
    int base = (threadIdx.x & 31) & ~3;   // quad leader lane

    // Gate rows for unit u: i=u, f=4+u, g=8+u, o=12+u.
    // Pair 0 = (i,f) scales (.5,.5); pair 1 = (g,o) scales (1,.5).
    const int   rlo[2] = { u,      8 + u };
    const int   rhi[2] = { 4 + u, 12 + u };
    const float slo[2] = { 0.5f, 1.0f };
    const float shi[2] = { 0.5f, 0.5f };

    ull wi0[2][2], wh0[2][4], b0[2];
    ull wi1[2][4], wh1[2][4], b1[2];
#pragma unroll
    for (int p = 0; p < 2; p++) {
        int lo = rlo[p], hi = rhi[p];
        float sl = slo[p], sh = shi[p];
#pragma unroll
        for (int k = 0; k < 2; k++)
            wi0[p][k] = pk2(sl * __ldg(&Wih0[lo * 2 + k]), sh * __ldg(&Wih0[hi * 2 + k]));
#pragma unroll
        for (int k = 0; k < 4; k++) {
            wh0[p][k] = pk2(sl * __ldg(&Whh0[lo * 4 + k]), sh * __ldg(&Whh0[hi * 4 + k]));
            wi1[p][k] = pk2(sl * __ldg(&Wih1[lo * 4 + k]), sh * __ldg(&Wih1[hi * 4 + k]));
            wh1[p][k] = pk2(sl * __ldg(&Whh1[lo * 4 + k]), sh * __ldg(&Whh1[hi * 4 + k]));
        }
        b0[p] = pk2(sl * (__ldg(&bih0[lo]) + __ldg(&bhh0[lo])),
                    sh * (__ldg(&bih0[hi]) + __ldg(&bhh0[hi])));
        b1[p] = pk2(sl * (__ldg(&bih1[lo]) + __ldg(&bhh1[lo])),
                    sh * (__ldg(&bih1[hi]) + __ldg(&bhh1[hi])));
    }

    // Per-element state
    float cc0[NE], cc1[NE], z[NE];
    float g0[NE][4], g1[NE][4];
#pragma unroll
    for (int e = 0; e < NE; e++) {
        cc0[e] = cc1[e] = z[e] = 0.f;
#pragma unroll
        for (int k = 0; k < 4; k++) { g0[e][k] = 0.f; g1[e][k] = 0.f; }
    }

    // x rows are contiguous: element eA+e starts at float4 offset e*25
    const float4* xb = reinterpret_cast<const float4*>(x + (size_t)eA * (T_STEPS * 2));

#pragma unroll 1
    for (int tt = 0; tt < T_STEPS / 2; ++tt) {
        float4 xv[NE];
#pragma unroll
        for (int e = 0; e < NE; e++) xv[e] = __ldg(&xb[tt + e * (T_STEPS / 2)]);
        float wo  = __ldg(&Wout[(2 * tt) * 4 + u]);
        float wo2 = __ldg(&Wout[(2 * tt + 1) * 4 + u]);

#pragma unroll
        for (int s = 0; s < 2; s++) {
            float hq0[NE], hq1[NE];

            // ---- layer 0: two element-pairs ----
#pragma unroll
            for (int ep = 0; ep < 2; ep++) {
                float yi[2], yf[2], yg[2], yo[2];
#pragma unroll
                for (int j = 0; j < 2; j++) {
                    int e = 2 * ep + j;
                    float x0 = s ? xv[e].z : xv[e].x;
                    float x1 = s ? xv[e].w : xv[e].y;
                    ull dh0 = pk2(g0[e][0], g0[e][0]), dh1 = pk2(g0[e][1], g0[e][1]);
                    ull dh2 = pk2(g0[e][2], g0[e][2]), dh3 = pk2(g0[e][3], g0[e][3]);
                    ull dx0 = pk2(x0, x0), dx1 = pk2(x1, x1);

                    ull a0 = ffma2(wh0[0][0], dh0, b0[0]);
                    ull a1 = ffma2(wh0[1][0], dh0, b0[1]);
                    a0 = ffma2(wh0[0][1], dh1, a0);  a1 = ffma2(wh0[1][1], dh1, a1);
                    a0 = ffma2(wh0[0][2], dh2, a0);  a1 = ffma2(wh0[1][2], dh2, a1);
                    a0 = ffma2(wh0[0][3], dh3, a0);  a1 = ffma2(wh0[1][3], dh3, a1);
                    a0 = ffma2(wi0[0][0], dx0, a0);  a1 = ffma2(wi0[1][0], dx0, a1);
                    a0 = ffma2(wi0[0][1], dx1, a0);  a1 = ffma2(wi0[1][1], dx1, a1);

                    upk2(a0, yi[j], yf[j]);
                    upk2(a1, yg[j], yo[j]);
                }
                float si[2], sf[2], so[2];
                sig2(yi[0], yi[1], si[0], si[1]);
                sig2(yf[0], yf[1], sf[0], sf[1]);
                sig2(yo[0], yo[1], so[0], so[1]);
#pragma unroll
                for (int j = 0; j < 2; j++) {
                    int e = 2 * ep + j;
                    float tg = tanhap(yg[j]);
                    cc0[e] = fmaf(sf[j], cc0[e], si[j] * tg);
                    hq0[e] = so[j] * tanhap(cc0[e]);
                }
            }

            // broadcast layer0 h across quad
#pragma unroll
            for (int e = 0; e < NE; e++) {
                g0[e][0] = __shfl_sync(0xFFFFFFFFu, hq0[e], base + 0);
                g0[e][1] = __shfl_sync(0xFFFFFFFFu, hq0[e], base + 1);
                g0[e][2] = __shfl_sync(0xFFFFFFFFu, hq0[e], base + 2);
                g0[e][3] = __shfl_sync(0xFFFFFFFFu, hq0[e], base + 3);
            }

            // ---- layer 1: recurrent (old g1) first, fresh g0 last ----
#pragma unroll
            for (int ep = 0; ep < 2; ep++) {
                float yi[2], yf[2], yg[2], yo[2];
#pragma unroll
                for (int j = 0; j < 2; j++) {
                    int e = 2 * ep + j;
                    ull f0 = pk2(g1[e][0], g1[e][0]), f1 = pk2(g1[e][1], g1[e][1]);
                    ull f2 = pk2(g1[e][2], g1[e][2]), f3 = pk2(g1[e][3], g1[e][3]);

                    ull m0 = ffma2(wh1[0][0], f0, b1[0]);
                    ull m1 = ffma2(wh1[1][0], f0, b1[1]);
                    m0 = ffma2(wh1[0][1], f1, m0);  m1 = ffma2(wh1[1][1], f1, m1);
                    m0 = ffma2(wh1[0][2], f2, m0);  m1 = ffma2(wh1[1][2], f2, m1);
                    m0 = ffma2(wh1[0][3], f3, m0);  m1 = ffma2(wh1[1][3], f3, m1);

                    ull e0 = pk2(g0[e][0], g0[e][0]), e1 = pk2(g0[e][1], g0[e][1]);
                    ull e2 = pk2(g0[e][2], g0[e][2]), e3 = pk2(g0[e][3], g0[e][3]);
                    m0 = ffma2(wi1[0][0], e0, m0);  m1 = ffma2(wi1[1][0], e0, m1);
                    m0 = ffma2(wi1[0][1], e1, m0);  m1 = ffma2(wi1[1][1], e1, m1);
                    m0 = ffma2(wi1[0][2], e2, m0);  m1 = ffma2(wi1[1][2], e2, m1);
                    m0 = ffma2(wi1[0][3], e3, m0);  m1 = ffma2(wi1[1][3], e3, m1);

                    upk2(m0, yi[j], yf[j]);
                    upk2(m1, yg[j], yo[j]);
                }
                float si[2], sf[2], so[2];
                sig2(yi[0], yi[1], si[0], si[1]);
                sig2(yf[0], yf[1], sf[0], sf[1]);
                sig2(yo[0], yo[1], so[0], so[1]);
#pragma unroll
                for (int j = 0; j < 2; j++) {
                    int e = 2 * ep + j;
                    float tg = tanhap(yg[j]);
                    cc1[e] = fmaf(sf[j], cc1[e], si[j] * tg);
                    hq1[e] = so[j] * tanhap(cc1[e]);
                    z[e] = fmaf(hq1[e], s ? wo2 : wo, z[e]);
                }
            }

            // broadcast layer1 h for next step's recurrence
#pragma unroll
            for (int e = 0; e < NE; e++) {
                g1[e][0] = __shfl_sync(0xFFFFFFFFu, hq1[e], base + 0);
                g1[e][1] = __shfl_sync(0xFFFFFFFFu, hq1[e], base + 1);
                g1[e][2] = __shfl_sync(0xFFFFFFFFu, hq1[e], base + 2);
                g1[e][3] = __shfl_sync(0xFFFFFFFFu, hq1[e], base + 3);
            }
        }
    }

    // quad reduction of readouts; lane u==0 stores a coalesced float4
#pragma unroll
    for (int e = 0; e < NE; e++) {
        z[e] += __shfl_xor_sync(0xFFFFFFFFu, z[e], 1);
        z[e] += __shfl_xor_sync(0xFFFFFFFFu, z[e], 2);
    }
    if (u == 0) {
        float bo = __ldg(&bout[0]);
        float4 r;
        r.x = rcpf(1.0f + ex2f(-1.442695040888963f * (z[0] + bo)));
        r.y = rcpf(1.0f + ex2f(-1.442695040888963f * (z[1] + bo)));
        r.z = rcpf(1.0f + ex2f(-1.442695040888963f * (z[2] + bo)));
        r.w = rcpf(1.0f + ex2f(-1.442695040888963f * (z[3] + bo)));
        *reinterpret_cast<float4*>(out + eA) = r;
    }
}

// ---------------------------------------------------------------------------
extern "C" void kernel_launch(void* const* d_in, const int* in_sizes, int n_in,
                              void* d_out, int out_size)
{
    const float* x    = (const float*)d_in[0];
    const float* Wih0 = (const float*)d_in[1];
    const float* Whh0 = (const float*)d_in[2];
    const float* bih0 = (const float*)d_in[3];
    const float* bhh0 = (const float*)d_in[4];
    const float* Wih1 = (const float*)d_in[5];
    const float* Whh1 = (const float*)d_in[6];
    const float* bih1 = (const float*)d_in[7];
    const float* bhh1 = (const float*)d_in[8];
    const float* Wout = (const float*)d_in[9];
    const float* bout = (const float*)d_in[10];

    int B = in_sizes[0] / (T_STEPS * 2);
    int threads = B;                   // 4 lanes per 4 elements
    int grid = (threads + 127) / 128;

    lstm_fused4h<<<grid, 128>>>(x, Wih0, Whh0, bih0, bhh0,
                                Wih1, Whh1, bih1, bhh1,
                                Wout, bout, (float*)d_out, B);
}